// round 9
// baseline (speedup 1.0000x reference)
#include <cuda_runtime.h>
#include <math.h>
#include <stdint.h>

#define N_NODES 1024
#define BATCH   32
#define T_ENC   12
#define HORIZON 12
#define HID     64
#define RBN     (N_NODES * BATCH)   // 32768 rows (n*B+b)

// ---------------- device scratch (no allocations allowed) ----------------
__device__ float g_Ss_hi[2 * N_NODES * N_NODES]; // stacked supports, tf32-hi plane
__device__ float g_Ss_lo[2 * N_NODES * N_NODES]; // stacked supports, tf32-lo plane
__device__ float g_rs[N_NODES];
__device__ float g_cs[N_NODES];
__device__ float g_xs[RBN * 5 * 128];           // [n][b][slot(5)][F<=128]
__device__ float g_ru[RBN * 128];               // r = cols 0..63, u = cols 64..127
__device__ float g_h0[RBN * HID];
__device__ float g_h1[RBN * HID];
__device__ float g_out0[T_ENC * RBN * HID];     // encoder layer-0 outputs per t
__device__ float g_src[T_ENC * RBN * 2];        // source re-laid out [t][n][b][2]
__device__ float g_y[RBN];                      // decoder feedback [n][b][1]

// ---------------- tf32 split helpers ----------------
__device__ __forceinline__ void split_tf32(float v, float& hi, float& lo) {
    uint32_t h;
    asm("cvt.rna.tf32.f32 %0, %1;" : "=r"(h) : "f"(v));
    float hf = __uint_as_float(h);
    float lf = v - hf;
    uint32_t l;
    asm("cvt.rna.tf32.f32 %0, %1;" : "=r"(l) : "f"(lf));
    hi = hf;
    lo = __uint_as_float(l);
}

__device__ __forceinline__ void mma_tf32(float* c, const uint32_t* a, const uint32_t* b) {
    asm volatile(
        "mma.sync.aligned.m16n8k8.row.col.f32.tf32.tf32.f32 "
        "{%0,%1,%2,%3}, {%4,%5,%6,%7}, {%8,%9}, {%0,%1,%2,%3};"
        : "+f"(c[0]), "+f"(c[1]), "+f"(c[2]), "+f"(c[3])
        : "r"(a[0]), "r"(a[1]), "r"(a[2]), "r"(a[3]), "r"(b[0]), "r"(b[1]));
}

// float-index alignment (mod 4) of a float pointer
__device__ __forceinline__ int fal4(const float* p) {
    return (int)((((uintptr_t)p) >> 2) & 3);
}

// ---------------- precompute kernels ----------------
__global__ void rowsum_k(const float* __restrict__ A) {
    __shared__ float sh[256];
    int row = blockIdx.x;
    float s = 0.f;
    for (int j = threadIdx.x; j < N_NODES; j += 256) s += A[row * N_NODES + j];
    sh[threadIdx.x] = s;
    __syncthreads();
    for (int o = 128; o > 0; o >>= 1) {
        if (threadIdx.x < o) sh[threadIdx.x] += sh[threadIdx.x + o];
        __syncthreads();
    }
    if (threadIdx.x == 0) g_rs[row] = sh[0];
}

__global__ void colsum_k(const float* __restrict__ A) {
    int c = blockIdx.x * blockDim.x + threadIdx.x;
    if (c >= N_NODES) return;
    float s = 0.f;
    for (int m = 0; m < N_NODES; m++) s += A[m * N_NODES + c];
    g_cs[c] = s;
}

// S0[m][n] = A[n][m]/max(rowsum(n),1e-8)   (RW(A)^T)
// S1[m][n] = A[m][n]/max(colsum(n),1e-8)   (RW(A^T)^T)
// Stored pre-split into tf32 hi/lo planes (S is static across all 384 GEMM launches).
__global__ void build_S(const float* __restrict__ A) {
    int idx = blockIdx.x * blockDim.x + threadIdx.x;
    if (idx >= N_NODES * N_NODES) return;
    int m = idx >> 10, n = idx & 1023;
    float s0 = A[n * N_NODES + m] / fmaxf(g_rs[n], 1e-8f);
    float s1 = A[m * N_NODES + n] / fmaxf(g_cs[n], 1e-8f);
    float h, l;
    split_tf32(s0, h, l);
    g_Ss_hi[idx] = h; g_Ss_lo[idx] = l;
    split_tf32(s1, h, l);
    g_Ss_hi[N_NODES * N_NODES + idx] = h;
    g_Ss_lo[N_NODES * N_NODES + idx] = l;
}

// source [B][T][N][2] -> g_src [t][n][b][2]
__global__ void src_tr(const float* __restrict__ src) {
    int idx = blockIdx.x * blockDim.x + threadIdx.x;
    const int total = T_ENC * RBN * 2;
    if (idx >= total) return;
    int f = idx & 1;
    int r = idx >> 1;
    int b = r & 31; r >>= 5;
    int n = r & 1023;
    int t = r >> 10;
    g_src[idx] = src[((b * T_ENC + t) * N_NODES + n) * 2 + f];
}

// concat([x, h]) into slot 0 of g_xs.  x: [n][b][IN], h: [n][b][64].
__global__ void concat_k(float* __restrict__ xs, const float* __restrict__ x,
                         const float* __restrict__ h, int IN, int F) {
    int idx = blockIdx.x * blockDim.x + threadIdx.x;
    int total = RBN * F;
    if (idx >= total) return;
    int f = idx % F;
    int rb = idx / F;
    float v = (f < IN) ? x[rb * IN + f] : h[rb * HID + (f - IN)];
    xs[rb * (5 * F) + f] = v;   // slot 0
}

// write only the h part of slot 0: xs[.., IN + j] = r * h   (x part already present)
__global__ void concat_h_k(float* __restrict__ xs, const float* __restrict__ h,
                           const float* __restrict__ ru, int IN, int F) {
    int idx = blockIdx.x * blockDim.x + threadIdx.x;
    if (idx >= RBN * HID) return;
    int j = idx % HID;
    int rb = idx / HID;
    xs[rb * (5 * F) + IN + j] = h[rb * HID + j] * ru[rb * 128 + j];  // r part
}

// ---------------- diffusion GEMM: C = alpha*(S @ X) [- X0] ----------------
// Stacked S (2048 x 1024), pre-split hi/lo. blockIdx.y < 8 -> S0 half (Xa -> Ca),
// else S1 half (Xb -> Cb). Column window: logical col c in [0, 32*Fsub) maps to
// feature colStart + c%Fsub of batch cb=c/Fsub -> xs offset cb*5F + colStart + c%Fsub;
// row stride ldn = 160*F (multiple of 4 floats, so base alignment is K-invariant).
// Compute: tensor-core tf32 with hi/lo split (acc += Ah*Bh + Al*Bh + Ah*Bl).
// CTA tile 128x128x8, 8 warps as 4(M) x 2(N); warp tile 32x64 = 2 m16 x 8 n8 mma tiles.
#define SMP 136   // smem row stride: 136 % 32 == 8 -> conflict-free fragment LDS
__global__ void __launch_bounds__(256, 2) diff_gemm(
    const float* __restrict__ Xa, const float* __restrict__ Xb,
    float* __restrict__ Ca, float* __restrict__ Cb,
    const float* __restrict__ X0, int F, int Fsub, int colStart, float alpha) {
    const int ldn = 160 * F;
    const int Ccols = BATCH * Fsub;
    __shared__ float Ah[2][8][SMP], Al[2][8][SMP];
    __shared__ float Bh[2][8][SMP], Bl[2][8][SMP];
    int t = threadIdx.x;
    int by = blockIdx.y;
    int half = by >> 3;
    const float* X = half ? Xb : Xa;
    float* C = half ? Cb : Ca;
    int bm = (by & 7) * 128;
    int bn = blockIdx.x * 128;

    int lane = t & 31;
    int wid = t >> 5;
    int wm = (wid & 3) * 32;    // warp M offset in tile
    int wn = (wid >> 2) * 64;   // warp N offset in tile

    // B-tile load mapping (column offsets are K-invariant)
    int lbk = t >> 5;            // 0..7
    int lbc = (t & 31) << 2;     // 0,4,...,124
    int boff[4];
#pragma unroll
    for (int j = 0; j < 4; j++) {
        int c = bn + lbc + j;
        if (c < Ccols) { int cb = c / Fsub; boff[j] = cb * 5 * F + colStart + (c - cb * Fsub); }
        else boff[j] = -1;
    }
    // contiguous group AND 16B-aligned FULL ADDRESS (base + offset) -> single LDG.128
    bool vec4 = (boff[0] >= 0) && (boff[3] == boff[0] + 3) &&
                (((fal4(X) + boff[0]) & 3) == 0);

    int am = t >> 1;             // 0..127 (A row within tile)
    int ak = (t & 1) << 2;       // 0 or 4
    const float* ArowH = g_Ss_hi + (by * 128 + am) * N_NODES + ak;
    const float* ArowL = g_Ss_lo + (by * 128 + am) * N_NODES + ak;

    float acc[2][8][4];
#pragma unroll
    for (int mi = 0; mi < 2; mi++)
#pragma unroll
        for (int ni = 0; ni < 8; ni++)
#pragma unroll
            for (int q = 0; q < 4; q++) acc[mi][ni][q] = 0.f;

    // prologue: load K-tile 0 into buffer 0
    {
        float4 ah = *(const float4*)(ArowH);
        float4 al = *(const float4*)(ArowL);
        Ah[0][ak + 0][am] = ah.x; Ah[0][ak + 1][am] = ah.y;
        Ah[0][ak + 2][am] = ah.z; Ah[0][ak + 3][am] = ah.w;
        Al[0][ak + 0][am] = al.x; Al[0][ak + 1][am] = al.y;
        Al[0][ak + 2][am] = al.z; Al[0][ak + 3][am] = al.w;
        const float* Xk = X + lbk * ldn;
        float bvv[4];
        if (vec4) {
            float4 b4 = *(const float4*)(Xk + boff[0]);
            bvv[0] = b4.x; bvv[1] = b4.y; bvv[2] = b4.z; bvv[3] = b4.w;
        } else {
#pragma unroll
            for (int j = 0; j < 4; j++)
                bvv[j] = (boff[j] >= 0) ? __ldg(Xk + boff[j]) : 0.f;
        }
        float h, l;
#pragma unroll
        for (int j = 0; j < 4; j++) {
            split_tf32(bvv[j], h, l);
            Bh[0][lbk][lbc + j] = h; Bl[0][lbk][lbc + j] = l;
        }
    }
    __syncthreads();

    const int NT = N_NODES / 8;   // 128 K-tiles
    for (int kt = 0; kt < NT; kt++) {
        int cur = kt & 1;
        // prefetch next tile into registers (overlaps with compute below)
        float4 avh, avl;
        float bv[4];
        if (kt + 1 < NT) {
            int k0 = (kt + 1) * 8;
            avh = *(const float4*)(ArowH + k0);
            avl = *(const float4*)(ArowL + k0);
            const float* Xk = X + (k0 + lbk) * ldn;
            if (vec4) {
                float4 b4 = *(const float4*)(Xk + boff[0]);
                bv[0] = b4.x; bv[1] = b4.y; bv[2] = b4.z; bv[3] = b4.w;
            } else {
#pragma unroll
                for (int j = 0; j < 4; j++)
                    bv[j] = (boff[j] >= 0) ? __ldg(Xk + boff[j]) : 0.f;
            }
        }

        // ---- tensor-core compute on current tile ----
        int fr = lane >> 2;       // 0..7
        int fk = lane & 3;        // 0..3
        uint32_t ahf[2][4], alf[2][4];
#pragma unroll
        for (int mi = 0; mi < 2; mi++) {
            int m0 = wm + mi * 16 + fr;
            ahf[mi][0] = __float_as_uint(Ah[cur][fk][m0]);
            ahf[mi][1] = __float_as_uint(Ah[cur][fk][m0 + 8]);
            ahf[mi][2] = __float_as_uint(Ah[cur][fk + 4][m0]);
            ahf[mi][3] = __float_as_uint(Ah[cur][fk + 4][m0 + 8]);
            alf[mi][0] = __float_as_uint(Al[cur][fk][m0]);
            alf[mi][1] = __float_as_uint(Al[cur][fk][m0 + 8]);
            alf[mi][2] = __float_as_uint(Al[cur][fk + 4][m0]);
            alf[mi][3] = __float_as_uint(Al[cur][fk + 4][m0 + 8]);
        }
#pragma unroll
        for (int ni = 0; ni < 8; ni++) {
            int n0 = wn + ni * 8 + fr;
            uint32_t bhf[2], blf[2];
            bhf[0] = __float_as_uint(Bh[cur][fk][n0]);
            bhf[1] = __float_as_uint(Bh[cur][fk + 4][n0]);
            blf[0] = __float_as_uint(Bl[cur][fk][n0]);
            blf[1] = __float_as_uint(Bl[cur][fk + 4][n0]);
#pragma unroll
            for (int mi = 0; mi < 2; mi++) {
                mma_tf32(acc[mi][ni], ahf[mi], bhf);
                mma_tf32(acc[mi][ni], alf[mi], bhf);
                mma_tf32(acc[mi][ni], ahf[mi], blf);
            }
        }

        if (kt + 1 < NT) {
            int nxt = cur ^ 1;
            Ah[nxt][ak + 0][am] = avh.x; Ah[nxt][ak + 1][am] = avh.y;
            Ah[nxt][ak + 2][am] = avh.z; Ah[nxt][ak + 3][am] = avh.w;
            Al[nxt][ak + 0][am] = avl.x; Al[nxt][ak + 1][am] = avl.y;
            Al[nxt][ak + 2][am] = avl.z; Al[nxt][ak + 3][am] = avl.w;
            float h, l;
#pragma unroll
            for (int j = 0; j < 4; j++) {
                split_tf32(bv[j], h, l);
                Bh[nxt][lbk][lbc + j] = h; Bl[nxt][lbk][lbc + j] = l;
            }
        }
        __syncthreads();
    }

    // epilogue: c0=(r=lane/4, n=2*(lane%4)), c1=(r, n+1), c2=(r+8, n), c3=(r+8, n+1)
    int fr = lane >> 2;
    int fc = (lane & 3) << 1;
#pragma unroll
    for (int mi = 0; mi < 2; mi++) {
#pragma unroll
        for (int ni = 0; ni < 8; ni++) {
#pragma unroll
            for (int q = 0; q < 4; q++) {
                int m = bm + wm + mi * 16 + fr + ((q >> 1) << 3);
                int c = bn + wn + ni * 8 + fc + (q & 1);
                if (c >= Ccols) continue;
                int cb = c / Fsub;
                int off = cb * 5 * F + colStart + (c - cb * Fsub);
                float v = alpha * acc[mi][ni][q];
                if (X0) v -= X0[m * ldn + off];
                C[m * ldn + off] = v;
            }
        }
    }
}

// ---------------- projection GEMM (tensor-core tf32 split, same fragment maps) ----------
// out = act([32768 x K] @ [K x O] + bias), O = 128 (mode 0) or 64 (mode 1).
// mode 0: sigmoid -> ru[row][0..127]
// mode 1: c = tanh(.), h = u*h + (1-u)*c (in place), optional copy to out2
// Vector loads: A via LDG.128 when K % 8 == 0 (enc1/dec1: K=640; g_xs base and K-row
// offsets are then 16B-aligned); W rows never straddle K -> always vectorized with a
// whole-row guard.
template <int O>
__global__ void __launch_bounds__(256, 2) proj_gemm(
    const float* __restrict__ A, const float* __restrict__ W,
    const float* __restrict__ bias, int K, int mode,
    float* __restrict__ ru, float* __restrict__ h, float* __restrict__ out2) {
    constexpr int NI = O / 16;          // n8-tiles per warp (8 for O=128, 4 for O=64)
    constexpr int BL = O / 32;          // B cols loaded per thread (4 or 2)
    __shared__ float Ahs[2][8][SMP], Als[2][8][SMP];
    __shared__ float Bhs[2][8][SMP], Bls[2][8][SMP];
    int t = threadIdx.x;
    int r0 = blockIdx.x * 128;
    int lane = t & 31;
    int wid = t >> 5;
    int wm = (wid & 3) * 32;
    int wn = (wid >> 2) * (O / 2);

    int am = t >> 1;            // A row in tile (0..127)
    int ak = (t & 1) << 2;      // 0 or 4
    int lbk = t >> 5;           // B k-row (0..7)
    int lbc = lane * BL;        // B col base

    const bool kv = ((K & 7) == 0);          // K=640: aligned, unguarded vector A path
    const float* Arow = A + (r0 + am) * K;

    float acc[2][NI][4];
#pragma unroll
    for (int mi = 0; mi < 2; mi++)
#pragma unroll
        for (int ni = 0; ni < NI; ni++)
#pragma unroll
            for (int q = 0; q < 4; q++) acc[mi][ni][q] = 0.f;

    const int NT = (K + 7) / 8;

    // prologue: tile 0
    {
        float av[4];
        if (kv) {
            float4 a4 = *(const float4*)(Arow + ak);
            av[0] = a4.x; av[1] = a4.y; av[2] = a4.z; av[3] = a4.w;
        } else {
#pragma unroll
            for (int j = 0; j < 4; j++)
                av[j] = (ak + j < K) ? Arow[ak + j] : 0.f;
        }
        float h_, l_;
#pragma unroll
        for (int j = 0; j < 4; j++) {
            split_tf32(av[j], h_, l_);
            Ahs[0][ak + j][am] = h_; Als[0][ak + j][am] = l_;
        }
        // W row lbk (0..7) always < K (K >= 325)
        float wv[BL];
        if (BL == 4) {
            float4 w4 = *(const float4*)(W + lbk * O + lbc);
            wv[0] = w4.x; wv[1] = w4.y; wv[2] = w4.z; wv[3] = w4.w;
        } else {
            float2 w2 = *(const float2*)(W + lbk * O + lbc);
            wv[0] = w2.x; wv[1] = w2.y;
        }
#pragma unroll
        for (int j = 0; j < BL; j++) {
            split_tf32(wv[j], h_, l_);
            Bhs[0][lbk][lbc + j] = h_; Bls[0][lbk][lbc + j] = l_;
        }
    }
    __syncthreads();

    for (int kt = 0; kt < NT; kt++) {
        int cur = kt & 1;
        float avv[4], bvv[BL];
        if (kt + 1 < NT) {
            int k0 = (kt + 1) * 8;
            if (kv) {
                float4 a4 = *(const float4*)(Arow + k0 + ak);
                avv[0] = a4.x; avv[1] = a4.y; avv[2] = a4.z; avv[3] = a4.w;
            } else {
#pragma unroll
                for (int j = 0; j < 4; j++) {
                    int k = k0 + ak + j;
                    avv[j] = (k < K) ? Arow[k] : 0.f;
                }
            }
            int kb = k0 + lbk;
            if (kb < K) {     // whole W row valid or not — vector load stays in-bounds
                if (BL == 4) {
                    float4 w4 = *(const float4*)(W + kb * O + lbc);
                    bvv[0] = w4.x; bvv[1] = w4.y; bvv[2] = w4.z; bvv[3] = w4.w;
                } else {
                    float2 w2 = *(const float2*)(W + kb * O + lbc);
                    bvv[0] = w2.x; bvv[1] = w2.y;
                }
            } else {
#pragma unroll
                for (int j = 0; j < BL; j++) bvv[j] = 0.f;
            }
        }

        int fr = lane >> 2;
        int fk = lane & 3;
        uint32_t ahf[2][4], alf[2][4];
#pragma unroll
        for (int mi = 0; mi < 2; mi++) {
            int m0 = wm + mi * 16 + fr;
            ahf[mi][0] = __float_as_uint(Ahs[cur][fk][m0]);
            ahf[mi][1] = __float_as_uint(Ahs[cur][fk][m0 + 8]);
            ahf[mi][2] = __float_as_uint(Ahs[cur][fk + 4][m0]);
            ahf[mi][3] = __float_as_uint(Ahs[cur][fk + 4][m0 + 8]);
            alf[mi][0] = __float_as_uint(Als[cur][fk][m0]);
            alf[mi][1] = __float_as_uint(Als[cur][fk][m0 + 8]);
            alf[mi][2] = __float_as_uint(Als[cur][fk + 4][m0]);
            alf[mi][3] = __float_as_uint(Als[cur][fk + 4][m0 + 8]);
        }
#pragma unroll
        for (int ni = 0; ni < NI; ni++) {
            int n0 = wn + ni * 8 + fr;
            uint32_t bhf[2], blf[2];
            bhf[0] = __float_as_uint(Bhs[cur][fk][n0]);
            bhf[1] = __float_as_uint(Bhs[cur][fk + 4][n0]);
            blf[0] = __float_as_uint(Bls[cur][fk][n0]);
            blf[1] = __float_as_uint(Bls[cur][fk + 4][n0]);
#pragma unroll
            for (int mi = 0; mi < 2; mi++) {
                mma_tf32(acc[mi][ni], ahf[mi], bhf);
                mma_tf32(acc[mi][ni], alf[mi], bhf);
                mma_tf32(acc[mi][ni], ahf[mi], blf);
            }
        }

        if (kt + 1 < NT) {
            int nxt = cur ^ 1;
            float h_, l_;
#pragma unroll
            for (int j = 0; j < 4; j++) {
                split_tf32(avv[j], h_, l_);
                Ahs[nxt][ak + j][am] = h_; Als[nxt][ak + j][am] = l_;
            }
#pragma unroll
            for (int j = 0; j < BL; j++) {
                split_tf32(bvv[j], h_, l_);
                Bhs[nxt][lbk][lbc + j] = h_; Bls[nxt][lbk][lbc + j] = l_;
            }
        }
        __syncthreads();
    }

    // epilogue
    int fr = lane >> 2;
    int fc = (lane & 3) << 1;
#pragma unroll
    for (int mi = 0; mi < 2; mi++) {
#pragma unroll
        for (int ni = 0; ni < NI; ni++) {
#pragma unroll
            for (int q = 0; q < 4; q++) {
                int row = r0 + wm + mi * 16 + fr + ((q >> 1) << 3);
                int c = wn + ni * 8 + fc + (q & 1);
                float v = acc[mi][ni][q] + bias[c];
                if (mode == 0) {
                    ru[row * 128 + c] = 1.f / (1.f + expf(-v));
                } else {
                    float cv = tanhf(v);
                    float u = ru[row * 128 + 64 + c];
                    float hv = h[row * HID + c];
                    float hn = u * hv + (1.f - u) * cv;
                    h[row * HID + c] = hn;
                    if (out2) out2[row * HID + c] = hn;
                }
            }
        }
    }
}

// ---------------- final projection: y = h1 @ fcn_W + fcn_b ----------------
__global__ void fcn_k(const float* __restrict__ h1, const float* __restrict__ W,
                      const float* __restrict__ b, float* __restrict__ y,
                      float* __restrict__ dout) {
    int gid = blockIdx.x * blockDim.x + threadIdx.x;
    int row = gid >> 5;
    int lane = gid & 31;
    if (row >= RBN) return;
    float s = h1[row * HID + lane] * W[lane] + h1[row * HID + 32 + lane] * W[32 + lane];
#pragma unroll
    for (int o = 16; o > 0; o >>= 1) s += __shfl_down_sync(0xFFFFFFFFu, s, o);
    if (lane == 0) {
        float v = s + b[0];
        y[row] = v;
        int n = row >> 5, bb = row & 31;
        dout[bb * N_NODES + n] = v;
    }
}

// ---------------- host orchestration ----------------
static void run_cell(const float* x, int IN,
                     const float* Wru, const float* bru,
                     const float* Wc, const float* bc,
                     float* xs, float* ru, float* h, float* out2) {
    int F = IN + HID;
    float* s0 = xs;
    float* s1 = xs + F;
    float* s2 = xs + 2 * F;
    float* s3 = xs + 3 * F;
    float* s4 = xs + 4 * F;

    // r,u gate gconv: full F columns
    {
        dim3 cgrid((RBN * F + 255) / 256);
        dim3 dgrid((BATCH * F + 127) / 128, 16);
        concat_k<<<cgrid, 256>>>(xs, x, h, IN, F);
        diff_gemm<<<dgrid, 256>>>(s0, s0, s1, s3, nullptr, F, F, 0, 1.f);
        diff_gemm<<<dgrid, 256>>>(s1, s3, s2, s4, s0, F, F, 0, 2.f);
        proj_gemm<128><<<256, 256>>>(xs, Wru, bru, 5 * F, 0, ru, nullptr, nullptr);
    }

    // candidate gconv: only h-columns need re-diffusion (x-cols unchanged in slots 1..4)
    {
        dim3 cgrid((RBN * HID + 255) / 256);
        dim3 dgrid((BATCH * HID + 127) / 128, 16);   // 16 x-tiles of 2048 cols
        concat_h_k<<<cgrid, 256>>>(xs, h, ru, IN, F);
        diff_gemm<<<dgrid, 256>>>(s0, s0, s1, s3, nullptr, F, HID, IN, 1.f);
        diff_gemm<<<dgrid, 256>>>(s1, s3, s2, s4, s0, F, HID, IN, 2.f);
        proj_gemm<64><<<256, 256>>>(xs, Wc, bc, 5 * F, 1, ru, h, out2);
    }
}

extern "C" void kernel_launch(void* const* d_in, const int* in_sizes, int n_in,
                              void* d_out, int out_size) {
    const float* adj    = (const float*)d_in[0];
    const float* source = (const float*)d_in[1];
    const float* e0Wru = (const float*)d_in[3];
    const float* e0bru = (const float*)d_in[4];
    const float* e0Wc  = (const float*)d_in[5];
    const float* e0bc  = (const float*)d_in[6];
    const float* e1Wru = (const float*)d_in[7];
    const float* e1bru = (const float*)d_in[8];
    const float* e1Wc  = (const float*)d_in[9];
    const float* e1bc  = (const float*)d_in[10];
    const float* d0Wru = (const float*)d_in[11];
    const float* d0bru = (const float*)d_in[12];
    const float* d0Wc  = (const float*)d_in[13];
    const float* d0bc  = (const float*)d_in[14];
    const float* d1Wru = (const float*)d_in[15];
    const float* d1bru = (const float*)d_in[16];
    const float* d1Wc  = (const float*)d_in[17];
    const float* d1bc  = (const float*)d_in[18];
    const float* fcnW  = (const float*)d_in[19];
    const float* fcnb  = (const float*)d_in[20];

    float *xs, *ru, *h0, *h1, *out0, *src, *y;
    cudaGetSymbolAddress((void**)&xs,   g_xs);
    cudaGetSymbolAddress((void**)&ru,   g_ru);
    cudaGetSymbolAddress((void**)&h0,   g_h0);
    cudaGetSymbolAddress((void**)&h1,   g_h1);
    cudaGetSymbolAddress((void**)&out0, g_out0);
    cudaGetSymbolAddress((void**)&src,  g_src);
    cudaGetSymbolAddress((void**)&y,    g_y);

    // supports + layout transforms
    rowsum_k<<<N_NODES, 256>>>(adj);
    colsum_k<<<(N_NODES + 255) / 256, 256>>>(adj);
    build_S<<<(N_NODES * N_NODES + 255) / 256, 256>>>(adj);
    src_tr<<<(T_ENC * RBN * 2 + 255) / 256, 256>>>(source);

    cudaMemsetAsync(h0, 0, RBN * HID * sizeof(float));
    cudaMemsetAsync(h1, 0, RBN * HID * sizeof(float));

    // ---- encoder ----
    for (int t = 0; t < T_ENC; t++)
        run_cell(src + t * RBN * 2, 2, e0Wru, e0bru, e0Wc, e0bc,
                 xs, ru, h0, out0 + t * RBN * HID);
    for (int t = 0; t < T_ENC; t++)
        run_cell(out0 + t * RBN * HID, HID, e1Wru, e1bru, e1Wc, e1bc,
                 xs, ru, h1, nullptr);

    // ---- decoder (teaching_force_ratio = 0) ----
    cudaMemsetAsync(y, 0, RBN * sizeof(float));
    float* dout = (float*)d_out;
    for (int t = 0; t < HORIZON; t++) {
        run_cell(y, 1, d0Wru, d0bru, d0Wc, d0bc, xs, ru, h0, nullptr);
        run_cell(h0, HID, d1Wru, d1bru, d1Wc, d1bc, xs, ru, h1, nullptr);
        fcn_k<<<(RBN * 32 + 255) / 256, 256>>>(h1, fcnW, fcnb, y,
                                               dout + t * BATCH * N_NODES);
    }
}

// round 14
// speedup vs baseline: 1.0483x; 1.0483x over previous
#include <cuda_runtime.h>
#include <math.h>
#include <stdint.h>

#define N_NODES 1024
#define BATCH   32
#define T_ENC   12
#define HORIZON 12
#define HID     64
#define RBN     (N_NODES * BATCH)   // 32768 rows (n*B+b)

// ---------------- device scratch (no allocations allowed) ----------------
// Packed pre-split supports: g_Sp[((s*1024+m)*128+kt)*4 + j] =
//   (hi(S_s[m][kt*8+j]), lo(..), hi(S_s[m][kt*8+j+4]), lo(..)),  j in 0..3
__device__ float4 g_Sp[2 * N_NODES * 128 * 4];
__device__ float g_rs[N_NODES];
__device__ float g_cs[N_NODES];
__device__ float g_xs[RBN * 5 * 128];           // [n][b][slot(5)][F<=128]
__device__ float g_ru[RBN * 128];               // r = cols 0..63, u = cols 64..127
__device__ float g_h0[RBN * HID];
__device__ float g_h1[RBN * HID];
__device__ float g_out0[T_ENC * RBN * HID];     // encoder layer-0 outputs per t
__device__ float g_src[T_ENC * RBN * 2];        // source re-laid out [t][n][b][2]
__device__ float g_y[RBN];                      // decoder feedback [n][b][1]

// ---------------- tf32 split helpers ----------------
__device__ __forceinline__ void split_tf32(float v, float& hi, float& lo) {
    uint32_t h;
    asm("cvt.rna.tf32.f32 %0, %1;" : "=r"(h) : "f"(v));
    float hf = __uint_as_float(h);
    float lf = v - hf;
    uint32_t l;
    asm("cvt.rna.tf32.f32 %0, %1;" : "=r"(l) : "f"(lf));
    hi = hf;
    lo = __uint_as_float(l);
}

__device__ __forceinline__ void mma_tf32(float* c, const uint32_t* a, const uint32_t* b) {
    asm volatile(
        "mma.sync.aligned.m16n8k8.row.col.f32.tf32.tf32.f32 "
        "{%0,%1,%2,%3}, {%4,%5,%6,%7}, {%8,%9}, {%0,%1,%2,%3};"
        : "+f"(c[0]), "+f"(c[1]), "+f"(c[2]), "+f"(c[3])
        : "r"(a[0]), "r"(a[1]), "r"(a[2]), "r"(a[3]), "r"(b[0]), "r"(b[1]));
}

// float-index alignment (mod 4) of a float pointer
__device__ __forceinline__ int fal4(const float* p) {
    return (int)((((uintptr_t)p) >> 2) & 3);
}

// ---------------- precompute kernels ----------------
__global__ void rowsum_k(const float* __restrict__ A) {
    __shared__ float sh[256];
    int row = blockIdx.x;
    float s = 0.f;
    for (int j = threadIdx.x; j < N_NODES; j += 256) s += A[row * N_NODES + j];
    sh[threadIdx.x] = s;
    __syncthreads();
    for (int o = 128; o > 0; o >>= 1) {
        if (threadIdx.x < o) sh[threadIdx.x] += sh[threadIdx.x + o];
        __syncthreads();
    }
    if (threadIdx.x == 0) g_rs[row] = sh[0];
}

__global__ void colsum_k(const float* __restrict__ A) {
    int c = blockIdx.x * blockDim.x + threadIdx.x;
    if (c >= N_NODES) return;
    float s = 0.f;
    for (int m = 0; m < N_NODES; m++) s += A[m * N_NODES + c];
    g_cs[c] = s;
}

// S0[m][n] = A[n][m]/max(rowsum(n),1e-8)   (RW(A)^T)
// S1[m][n] = A[m][n]/max(colsum(n),1e-8)   (RW(A^T)^T)
// Written pre-split AND pre-packed into MMA-fragment float4s (see g_Sp comment).
__global__ void build_S(const float* __restrict__ A) {
    int idx = blockIdx.x * blockDim.x + threadIdx.x;   // over 1024*128*4
    if (idx >= N_NODES * 128 * 4) return;
    int j = idx & 3;
    int kt = (idx >> 2) & 127;
    int m = idx >> 9;
    int n1 = kt * 8 + j;
    int n2 = n1 + 4;
    {
        float v1 = A[n1 * N_NODES + m] / fmaxf(g_rs[n1], 1e-8f);
        float v2 = A[n2 * N_NODES + m] / fmaxf(g_rs[n2], 1e-8f);
        float h1, l1, h2, l2;
        split_tf32(v1, h1, l1);
        split_tf32(v2, h2, l2);
        g_Sp[(m * 128 + kt) * 4 + j] = make_float4(h1, l1, h2, l2);
    }
    {
        float v1 = A[m * N_NODES + n1] / fmaxf(g_cs[n1], 1e-8f);
        float v2 = A[m * N_NODES + n2] / fmaxf(g_cs[n2], 1e-8f);
        float h1, l1, h2, l2;
        split_tf32(v1, h1, l1);
        split_tf32(v2, h2, l2);
        g_Sp[((N_NODES + m) * 128 + kt) * 4 + j] = make_float4(h1, l1, h2, l2);
    }
}

// source [B][T][N][2] -> g_src [t][n][b][2]; also zero h0/h1/y.
__global__ void src_tr_init(const float* __restrict__ src) {
    int idx = blockIdx.x * blockDim.x + threadIdx.x;
    const int total = T_ENC * RBN * 2;
    if (idx < total) {
        int f = idx & 1;
        int r = idx >> 1;
        int b = r & 31; r >>= 5;
        int n = r & 1023;
        int t = r >> 10;
        g_src[idx] = src[((b * T_ENC + t) * N_NODES + n) * 2 + f];
    }
    for (int i = idx; i < RBN * HID; i += total) { g_h0[i] = 0.f; g_h1[i] = 0.f; }
    for (int i = idx; i < RBN; i += total) g_y[i] = 0.f;
}

// concat([x, h]) into slot 0 of g_xs.  x: [n][b][IN], h: [n][b][64]. (generic scalar)
__global__ void concat_k(float* __restrict__ xs, const float* __restrict__ x,
                         const float* __restrict__ h, int IN, int F) {
    int idx = blockIdx.x * blockDim.x + threadIdx.x;
    int total = RBN * F;
    if (idx >= total) return;
    int f = idx % F;
    int rb = idx / F;
    float v = (f < IN) ? x[rb * IN + f] : h[rb * HID + (f - IN)];
    xs[rb * (5 * F) + f] = v;   // slot 0
}

// fast path F==128, IN==64: fully float4 (all bases 16B-aligned, offsets mod 4 == 0)
__global__ void concat_v4(float* __restrict__ xs, const float* __restrict__ x,
                          const float* __restrict__ h) {
    int idx = blockIdx.x * blockDim.x + threadIdx.x;   // RBN*32 quads
    if (idx >= RBN * 32) return;
    int q = idx & 31;          // quad within row (0..31), f = q*4
    int rb = idx >> 5;
    float4 v = (q < 16) ? *(const float4*)(x + rb * 64 + q * 4)
                        : *(const float4*)(h + rb * 64 + (q - 16) * 4);
    *(float4*)(xs + rb * 640 + q * 4) = v;
}

// write only the h part of slot 0: xs[.., IN + j] = r * h   (generic scalar)
__global__ void concat_h_k(float* __restrict__ xs, const float* __restrict__ h,
                           const float* __restrict__ ru, int IN, int F) {
    int idx = blockIdx.x * blockDim.x + threadIdx.x;
    if (idx >= RBN * HID) return;
    int j = idx % HID;
    int rb = idx / HID;
    xs[rb * (5 * F) + IN + j] = h[rb * HID + j] * ru[rb * 128 + j];  // r part
}

// fast path F==128, IN==64: float4
__global__ void concat_h_v4(float* __restrict__ xs, const float* __restrict__ h,
                            const float* __restrict__ ru) {
    int idx = blockIdx.x * blockDim.x + threadIdx.x;   // RBN*16 quads
    if (idx >= RBN * 16) return;
    int q = idx & 15;
    int rb = idx >> 4;
    float4 hv = *(const float4*)(h + rb * 64 + q * 4);
    float4 rv = *(const float4*)(ru + rb * 128 + q * 4);
    float4 o;
    o.x = hv.x * rv.x; o.y = hv.y * rv.y; o.z = hv.z * rv.z; o.w = hv.w * rv.w;
    *(float4*)(xs + rb * 640 + 64 + q * 4) = o;
}

// ---------------- diffusion GEMM: C = alpha*(S @ X) [- X0] ----------------
// Stacked packed S (2048 x 1024). blockIdx.y < 8 -> S0 half (Xa -> Ca), else S1
// half (Xb -> Cb). Column window: logical col c in [0, 32*Fsub) maps to feature
// colStart + c%Fsub of batch cb=c/Fsub -> xs offset cb*5F + colStart + c%Fsub.
// A-path: fragment-packed float4 (hi,lo,hi+4,lo+4): LDG.128 -> STS.128 -> LDS.128,
// swizzle j^((m>>1)&3) (bank-enumerated conflict-free both directions).
// B-path: split at load into k-major hi/lo planes (SMP=136).
// MMA issue: ni-pair term-major (reuse distance 4), per-acc order hh->lh->hl.
#define SMP 136
__global__ void __launch_bounds__(256, 2) diff_gemm(
    const float* __restrict__ Xa, const float* __restrict__ Xb,
    float* __restrict__ Ca, float* __restrict__ Cb,
    const float* __restrict__ X0, int F, int Fsub, int colStart, float alpha) {
    const int ldn = 160 * F;
    const int Ccols = BATCH * Fsub;
    __shared__ float4 ApA[2][128][4];          // packed A fragments, swizzled cols
    __shared__ float Bh[2][8][SMP], Bl[2][8][SMP];
    int t = threadIdx.x;
    int by = blockIdx.y;
    int shalf = by >> 3;
    const float* X = shalf ? Xb : Xa;
    float* C = shalf ? Cb : Ca;
    int bm = (by & 7) * 128;
    int bn = blockIdx.x * 128;

    int lane = t & 31;
    int wid = t >> 5;
    int wm = (wid & 3) * 32;    // warp M offset in tile
    int wn = (wid >> 2) * 64;   // warp N offset in tile

    // B-tile load mapping (column offsets are K-invariant)
    int lbk = t >> 5;            // 0..7
    int lbc = (t & 31) << 2;     // 0,4,...,124
    int boff[4];
#pragma unroll
    for (int j = 0; j < 4; j++) {
        int c = bn + lbc + j;
        if (c < Ccols) { int cb = c / Fsub; boff[j] = cb * 5 * F + colStart + (c - cb * Fsub); }
        else boff[j] = -1;
    }
    bool vec4 = (boff[0] >= 0) && (boff[3] == boff[0] + 3) &&
                (((fal4(X) + boff[0]) & 3) == 0);

    // A loader: thread t handles row am = t>>1, float4 pair j0 = (t&1)*2 + {0,1}
    int am = t >> 1;
    int aj0 = (t & 1) * 2;
    int aswz = (am >> 1) & 3;
    const float4* Ap = g_Sp + (size_t)(by * 128 + am) * 512;   // 128 kt * 4 j

    float acc[2][8][4];
#pragma unroll
    for (int mi = 0; mi < 2; mi++)
#pragma unroll
        for (int ni = 0; ni < 8; ni++)
#pragma unroll
            for (int q = 0; q < 4; q++) acc[mi][ni][q] = 0.f;

    // prologue: K-tile 0 into buffer 0
    {
        float4 a0 = Ap[aj0 + 0];
        float4 a1 = Ap[aj0 + 1];
        ApA[0][am][(aj0 + 0) ^ aswz] = a0;
        ApA[0][am][(aj0 + 1) ^ aswz] = a1;
        const float* Xk = X + lbk * ldn;
        float bvv[4];
        if (vec4) {
            float4 b4 = *(const float4*)(Xk + boff[0]);
            bvv[0] = b4.x; bvv[1] = b4.y; bvv[2] = b4.z; bvv[3] = b4.w;
        } else {
#pragma unroll
            for (int j = 0; j < 4; j++)
                bvv[j] = (boff[j] >= 0) ? __ldg(Xk + boff[j]) : 0.f;
        }
        float h, l;
#pragma unroll
        for (int j = 0; j < 4; j++) {
            split_tf32(bvv[j], h, l);
            Bh[0][lbk][lbc + j] = h; Bl[0][lbk][lbc + j] = l;
        }
    }
    __syncthreads();

    const int NT = N_NODES / 8;   // 128 K-tiles
    for (int kt = 0; kt < NT; kt++) {
        int cur = kt & 1;
        // prefetch next tile into registers
        float4 a0n, a1n;
        float bv[4];
        if (kt + 1 < NT) {
            int kb = (kt + 1) * 4;
            a0n = Ap[kb + aj0 + 0];
            a1n = Ap[kb + aj0 + 1];
            const float* Xk = X + ((kt + 1) * 8 + lbk) * ldn;
            if (vec4) {
                float4 b4 = *(const float4*)(Xk + boff[0]);
                bv[0] = b4.x; bv[1] = b4.y; bv[2] = b4.z; bv[3] = b4.w;
            } else {
#pragma unroll
                for (int j = 0; j < 4; j++)
                    bv[j] = (boff[j] >= 0) ? __ldg(Xk + boff[j]) : 0.f;
            }
        }

        // ---- tensor-core compute on current tile ----
        int fr = lane >> 2;       // 0..7
        int fk = lane & 3;        // 0..3
        uint32_t ahf[2][4], alf[2][4];
#pragma unroll
        for (int mi = 0; mi < 2; mi++) {
            int m0 = wm + mi * 16 + fr;
            int sw = (fr >> 1) & 3;                     // == (m0>>1)&3, == ((m0+8)>>1)&3
            float4 fa = ApA[cur][m0][fk ^ sw];
            float4 fb = ApA[cur][m0 + 8][fk ^ sw];
            ahf[mi][0] = __float_as_uint(fa.x);
            ahf[mi][1] = __float_as_uint(fb.x);
            ahf[mi][2] = __float_as_uint(fa.z);
            ahf[mi][3] = __float_as_uint(fb.z);
            alf[mi][0] = __float_as_uint(fa.y);
            alf[mi][1] = __float_as_uint(fb.y);
            alf[mi][2] = __float_as_uint(fa.w);
            alf[mi][3] = __float_as_uint(fb.w);
        }
#pragma unroll
        for (int np = 0; np < 8; np += 2) {
            uint32_t bhf[2][2], blf[2][2];
#pragma unroll
            for (int u = 0; u < 2; u++) {
                int n0 = wn + (np + u) * 8 + fr;
                bhf[u][0] = __float_as_uint(Bh[cur][fk][n0]);
                bhf[u][1] = __float_as_uint(Bh[cur][fk + 4][n0]);
                blf[u][0] = __float_as_uint(Bl[cur][fk][n0]);
                blf[u][1] = __float_as_uint(Bl[cur][fk + 4][n0]);
            }
#pragma unroll
            for (int u = 0; u < 2; u++)
#pragma unroll
                for (int mi = 0; mi < 2; mi++)
                    mma_tf32(acc[mi][np + u], ahf[mi], bhf[u]);
#pragma unroll
            for (int u = 0; u < 2; u++)
#pragma unroll
                for (int mi = 0; mi < 2; mi++)
                    mma_tf32(acc[mi][np + u], alf[mi], bhf[u]);
#pragma unroll
            for (int u = 0; u < 2; u++)
#pragma unroll
                for (int mi = 0; mi < 2; mi++)
                    mma_tf32(acc[mi][np + u], ahf[mi], blf[u]);
        }

        if (kt + 1 < NT) {
            int nxt = cur ^ 1;
            ApA[nxt][am][(aj0 + 0) ^ aswz] = a0n;
            ApA[nxt][am][(aj0 + 1) ^ aswz] = a1n;
            float h, l;
#pragma unroll
            for (int j = 0; j < 4; j++) {
                split_tf32(bv[j], h, l);
                Bh[nxt][lbk][lbc + j] = h; Bl[nxt][lbk][lbc + j] = l;
            }
        }
        __syncthreads();
    }

    // epilogue
    int fr = lane >> 2;
    int fc = (lane & 3) << 1;
#pragma unroll
    for (int mi = 0; mi < 2; mi++) {
#pragma unroll
        for (int ni = 0; ni < 8; ni++) {
#pragma unroll
            for (int q = 0; q < 4; q++) {
                int m = bm + wm + mi * 16 + fr + ((q >> 1) << 3);
                int c = bn + wn + ni * 8 + fc + (q & 1);
                if (c >= Ccols) continue;
                int cb = c / Fsub;
                int off = cb * 5 * F + colStart + (c - cb * Fsub);
                float v = alpha * acc[mi][ni][q];
                if (X0) v -= X0[m * ldn + off];
                C[m * ldn + off] = v;
            }
        }
    }
}

// ---------------- projection GEMM (tensor-core tf32 split) ----------
template <int O>
__global__ void __launch_bounds__(256, 2) proj_gemm(
    const float* __restrict__ A, const float* __restrict__ W,
    const float* __restrict__ bias, int K, int mode,
    float* __restrict__ ru, float* __restrict__ h, float* __restrict__ out2) {
    constexpr int NI = O / 16;
    constexpr int BL = O / 32;
    __shared__ float Ahs[2][8][SMP], Als[2][8][SMP];
    __shared__ float Bhs[2][8][SMP], Bls[2][8][SMP];
    int t = threadIdx.x;
    int r0 = blockIdx.x * 128;
    int lane = t & 31;
    int wid = t >> 5;
    int wm = (wid & 3) * 32;
    int wn = (wid >> 2) * (O / 2);

    int am = t >> 1;
    int ak = (t & 1) << 2;
    int lbk = t >> 5;
    int lbc = lane * BL;

    const bool kv = ((K & 7) == 0);
    const float* Arow = A + (r0 + am) * K;

    float acc[2][NI][4];
#pragma unroll
    for (int mi = 0; mi < 2; mi++)
#pragma unroll
        for (int ni = 0; ni < NI; ni++)
#pragma unroll
            for (int q = 0; q < 4; q++) acc[mi][ni][q] = 0.f;

    const int NT = (K + 7) / 8;

    {
        float av[4];
        if (kv) {
            float4 a4 = *(const float4*)(Arow + ak);
            av[0] = a4.x; av[1] = a4.y; av[2] = a4.z; av[3] = a4.w;
        } else {
#pragma unroll
            for (int j = 0; j < 4; j++)
                av[j] = (ak + j < K) ? Arow[ak + j] : 0.f;
        }
        float h_, l_;
#pragma unroll
        for (int j = 0; j < 4; j++) {
            split_tf32(av[j], h_, l_);
            Ahs[0][ak + j][am] = h_; Als[0][ak + j][am] = l_;
        }
        float wv[BL];
        if (BL == 4) {
            float4 w4 = *(const float4*)(W + lbk * O + lbc);
            wv[0] = w4.x; wv[1] = w4.y; wv[2] = w4.z; wv[3] = w4.w;
        } else {
            float2 w2 = *(const float2*)(W + lbk * O + lbc);
            wv[0] = w2.x; wv[1] = w2.y;
        }
#pragma unroll
        for (int j = 0; j < BL; j++) {
            split_tf32(wv[j], h_, l_);
            Bhs[0][lbk][lbc + j] = h_; Bls[0][lbk][lbc + j] = l_;
        }
    }
    __syncthreads();

    for (int kt = 0; kt < NT; kt++) {
        int cur = kt & 1;
        float avv[4], bvv[BL];
        if (kt + 1 < NT) {
            int k0 = (kt + 1) * 8;
            if (kv) {
                float4 a4 = *(const float4*)(Arow + k0 + ak);
                avv[0] = a4.x; avv[1] = a4.y; avv[2] = a4.z; avv[3] = a4.w;
            } else {
#pragma unroll
                for (int j = 0; j < 4; j++) {
                    int k = k0 + ak + j;
                    avv[j] = (k < K) ? Arow[k] : 0.f;
                }
            }
            int kb = k0 + lbk;
            if (kb < K) {
                if (BL == 4) {
                    float4 w4 = *(const float4*)(W + kb * O + lbc);
                    bvv[0] = w4.x; bvv[1] = w4.y; bvv[2] = w4.z; bvv[3] = w4.w;
                } else {
                    float2 w2 = *(const float2*)(W + kb * O + lbc);
                    bvv[0] = w2.x; bvv[1] = w2.y;
                }
            } else {
#pragma unroll
                for (int j = 0; j < BL; j++) bvv[j] = 0.f;
            }
        }

        int fr = lane >> 2;
        int fk = lane & 3;
        uint32_t ahf[2][4], alf[2][4];
#pragma unroll
        for (int mi = 0; mi < 2; mi++) {
            int m0 = wm + mi * 16 + fr;
            ahf[mi][0] = __float_as_uint(Ahs[cur][fk][m0]);
            ahf[mi][1] = __float_as_uint(Ahs[cur][fk][m0 + 8]);
            ahf[mi][2] = __float_as_uint(Ahs[cur][fk + 4][m0]);
            ahf[mi][3] = __float_as_uint(Ahs[cur][fk + 4][m0 + 8]);
            alf[mi][0] = __float_as_uint(Als[cur][fk][m0]);
            alf[mi][1] = __float_as_uint(Als[cur][fk][m0 + 8]);
            alf[mi][2] = __float_as_uint(Als[cur][fk + 4][m0]);
            alf[mi][3] = __float_as_uint(Als[cur][fk + 4][m0 + 8]);
        }
#pragma unroll
        for (int np = 0; np < NI; np += 2) {
            uint32_t bhf[2][2], blf[2][2];
#pragma unroll
            for (int u = 0; u < 2; u++) {
                int n0 = wn + (np + u) * 8 + fr;
                bhf[u][0] = __float_as_uint(Bhs[cur][fk][n0]);
                bhf[u][1] = __float_as_uint(Bhs[cur][fk + 4][n0]);
                blf[u][0] = __float_as_uint(Bls[cur][fk][n0]);
                blf[u][1] = __float_as_uint(Bls[cur][fk + 4][n0]);
            }
#pragma unroll
            for (int u = 0; u < 2; u++)
#pragma unroll
                for (int mi = 0; mi < 2; mi++)
                    mma_tf32(acc[mi][np + u], ahf[mi], bhf[u]);
#pragma unroll
            for (int u = 0; u < 2; u++)
#pragma unroll
                for (int mi = 0; mi < 2; mi++)
                    mma_tf32(acc[mi][np + u], alf[mi], bhf[u]);
#pragma unroll
            for (int u = 0; u < 2; u++)
#pragma unroll
                for (int mi = 0; mi < 2; mi++)
                    mma_tf32(acc[mi][np + u], ahf[mi], blf[u]);
        }

        if (kt + 1 < NT) {
            int nxt = cur ^ 1;
            float h_, l_;
#pragma unroll
            for (int j = 0; j < 4; j++) {
                split_tf32(avv[j], h_, l_);
                Ahs[nxt][ak + j][am] = h_; Als[nxt][ak + j][am] = l_;
            }
#pragma unroll
            for (int j = 0; j < BL; j++) {
                split_tf32(bvv[j], h_, l_);
                Bhs[nxt][lbk][lbc + j] = h_; Bls[nxt][lbk][lbc + j] = l_;
            }
        }
        __syncthreads();
    }

    int fr = lane >> 2;
    int fc = (lane & 3) << 1;
#pragma unroll
    for (int mi = 0; mi < 2; mi++) {
#pragma unroll
        for (int ni = 0; ni < NI; ni++) {
#pragma unroll
            for (int q = 0; q < 4; q++) {
                int row = r0 + wm + mi * 16 + fr + ((q >> 1) << 3);
                int c = wn + ni * 8 + fc + (q & 1);
                float v = acc[mi][ni][q] + bias[c];
                if (mode == 0) {
                    ru[row * 128 + c] = 1.f / (1.f + expf(-v));
                } else {
                    float cv = tanhf(v);
                    float u = ru[row * 128 + 64 + c];
                    float hv = h[row * HID + c];
                    float hn = u * hv + (1.f - u) * cv;
                    h[row * HID + c] = hn;
                    if (out2) out2[row * HID + c] = hn;
                }
            }
        }
    }
}

// ---------------- final projection: y = h1 @ fcn_W + fcn_b ----------------
__global__ void fcn_k(const float* __restrict__ h1, const float* __restrict__ W,
                      const float* __restrict__ b, float* __restrict__ y,
                      float* __restrict__ dout) {
    int gid = blockIdx.x * blockDim.x + threadIdx.x;
    int row = gid >> 5;
    int lane = gid & 31;
    if (row >= RBN) return;
    float s = h1[row * HID + lane] * W[lane] + h1[row * HID + 32 + lane] * W[32 + lane];
#pragma unroll
    for (int o = 16; o > 0; o >>= 1) s += __shfl_down_sync(0xFFFFFFFFu, s, o);
    if (lane == 0) {
        float v = s + b[0];
        y[row] = v;
        int n = row >> 5, bb = row & 31;
        dout[bb * N_NODES + n] = v;
    }
}

// ---------------- host orchestration ----------------
static void run_cell(const float* x, int IN,
                     const float* Wru, const float* bru,
                     const float* Wc, const float* bc,
                     float* xs, float* ru, float* h, float* out2) {
    int F = IN + HID;
    float* s0 = xs;
    float* s1 = xs + F;
    float* s2 = xs + 2 * F;
    float* s3 = xs + 3 * F;
    float* s4 = xs + 4 * F;

    // r,u gate gconv: full F columns
    {
        dim3 dgrid((BATCH * F + 127) / 128, 16);
        if (F == 128)
            concat_v4<<<(RBN * 32 + 255) / 256, 256>>>(xs, x, h);
        else
            concat_k<<<(RBN * F + 255) / 256, 256>>>(xs, x, h, IN, F);
        diff_gemm<<<dgrid, 256>>>(s0, s0, s1, s3, nullptr, F, F, 0, 1.f);
        diff_gemm<<<dgrid, 256>>>(s1, s3, s2, s4, s0, F, F, 0, 2.f);
        proj_gemm<128><<<256, 256>>>(xs, Wru, bru, 5 * F, 0, ru, nullptr, nullptr);
    }

    // candidate gconv: only h-columns need re-diffusion (x-cols unchanged in slots 1..4)
    {
        dim3 dgrid((BATCH * HID + 127) / 128, 16);
        if (F == 128)
            concat_h_v4<<<(RBN * 16 + 255) / 256, 256>>>(xs, h, ru);
        else
            concat_h_k<<<(RBN * HID + 255) / 256, 256>>>(xs, h, ru, IN, F);
        diff_gemm<<<dgrid, 256>>>(s0, s0, s1, s3, nullptr, F, HID, IN, 1.f);
        diff_gemm<<<dgrid, 256>>>(s1, s3, s2, s4, s0, F, HID, IN, 2.f);
        proj_gemm<64><<<256, 256>>>(xs, Wc, bc, 5 * F, 1, ru, h, out2);
    }
}

extern "C" void kernel_launch(void* const* d_in, const int* in_sizes, int n_in,
                              void* d_out, int out_size) {
    const float* adj    = (const float*)d_in[0];
    const float* source = (const float*)d_in[1];
    const float* e0Wru = (const float*)d_in[3];
    const float* e0bru = (const float*)d_in[4];
    const float* e0Wc  = (const float*)d_in[5];
    const float* e0bc  = (const float*)d_in[6];
    const float* e1Wru = (const float*)d_in[7];
    const float* e1bru = (const float*)d_in[8];
    const float* e1Wc  = (const float*)d_in[9];
    const float* e1bc  = (const float*)d_in[10];
    const float* d0Wru = (const float*)d_in[11];
    const float* d0bru = (const float*)d_in[12];
    const float* d0Wc  = (const float*)d_in[13];
    const float* d0bc  = (const float*)d_in[14];
    const float* d1Wru = (const float*)d_in[15];
    const float* d1bru = (const float*)d_in[16];
    const float* d1Wc  = (const float*)d_in[17];
    const float* d1bc  = (const float*)d_in[18];
    const float* fcnW  = (const float*)d_in[19];
    const float* fcnb  = (const float*)d_in[20];

    float *xs, *ru, *h0, *h1, *out0, *src, *y;
    cudaGetSymbolAddress((void**)&xs,   g_xs);
    cudaGetSymbolAddress((void**)&ru,   g_ru);
    cudaGetSymbolAddress((void**)&h0,   g_h0);
    cudaGetSymbolAddress((void**)&h1,   g_h1);
    cudaGetSymbolAddress((void**)&out0, g_out0);
    cudaGetSymbolAddress((void**)&src,  g_src);
    cudaGetSymbolAddress((void**)&y,    g_y);

    // supports + layout transforms + state init
    rowsum_k<<<N_NODES, 256>>>(adj);
    colsum_k<<<(N_NODES + 255) / 256, 256>>>(adj);
    build_S<<<(N_NODES * 128 * 4 + 255) / 256, 256>>>(adj);
    src_tr_init<<<(T_ENC * RBN * 2 + 255) / 256, 256>>>(source);

    // ---- encoder ----
    for (int t = 0; t < T_ENC; t++)
        run_cell(src + t * RBN * 2, 2, e0Wru, e0bru, e0Wc, e0bc,
                 xs, ru, h0, out0 + t * RBN * HID);
    for (int t = 0; t < T_ENC; t++)
        run_cell(out0 + t * RBN * HID, HID, e1Wru, e1bru, e1Wc, e1bc,
                 xs, ru, h1, nullptr);

    // ---- decoder (teaching_force_ratio = 0; y zeroed in src_tr_init) ----
    float* dout = (float*)d_out;
    for (int t = 0; t < HORIZON; t++) {
        run_cell(y, 1, d0Wru, d0bru, d0Wc, d0bc, xs, ru, h0, nullptr);
        run_cell(h0, HID, d1Wru, d1bru, d1Wc, d1bc, xs, ru, h1, nullptr);
        fcn_k<<<(RBN * 32 + 255) / 256, 256>>>(h1, fcnW, fcnb, y,
                                               dout + t * BATCH * N_NODES);
    }
}